// round 2
// baseline (speedup 1.0000x reference)
#include <cuda_runtime.h>

#define NN 10000
#define EE 160000
#define GG 64
#define F_IN 128
#define C1D 128
#define C2D 256
#define C3D 512
#define KCH 5
#define NCLS 10
#define TXW (KCH * F_IN)   // 640

// ---------------- scratch (device globals; no allocation allowed) ----------
__device__ float g_deg_cheb[NN];
__device__ float g_deg_gcn[NN];
__device__ float g_dinv_cheb[NN];
__device__ float g_dinv_gcn[NN];
__device__ float g_TX[(size_t)NN * TXW];      // stacked Cheb Tx_k ; reused as GCN agg dest
__device__ float g_bufA[(size_t)NN * C3D];
__device__ float g_bufB[(size_t)NN * C3D];
__device__ float g_e[NN];                     // logits, then exp values
__device__ float g_gmax[GG];
__device__ float g_gsum[GG];
__device__ float g_pool[GG * C3D];

// ---------------- helpers ---------------------------------------------------
__device__ __forceinline__ void atomicMaxF(float* addr, float val) {
    int* ia = (int*)addr;
    int old = *ia;
    while (__int_as_float(old) < val) {
        int assumed = old;
        old = atomicCAS(ia, assumed, __float_as_int(val));
        if (old == assumed) break;
    }
}

// ---------------- degree / normalization -----------------------------------
__global__ void k_deg_init() {
    int i = blockIdx.x * blockDim.x + threadIdx.x;
    if (i < NN) { g_deg_cheb[i] = 0.f; g_deg_gcn[i] = 1.f; /* self loop */ }
}

__global__ void k_deg(const int* __restrict__ ei) {
    int e = blockIdx.x * blockDim.x + threadIdx.x;
    if (e >= EE) return;
    int s = ei[e];
    int d = ei[EE + e];
    atomicAdd(&g_deg_cheb[s], 1.f);
    atomicAdd(&g_deg_gcn[d], 1.f);
}

__global__ void k_dinv() {
    int i = blockIdx.x * blockDim.x + threadIdx.x;
    if (i >= NN) return;
    float dc = g_deg_cheb[i];
    g_dinv_cheb[i] = dc > 0.f ? rsqrtf(dc) : 0.f;
    g_dinv_gcn[i]  = rsqrtf(g_deg_gcn[i]);   // always >= 1
}

// ---------------- Cheb pipeline ---------------------------------------------
__global__ void k_copy_x(const float* __restrict__ x) {
    int idx = blockIdx.x * blockDim.x + threadIdx.x;   // over NN * (F_IN/4)
    if (idx >= NN * (F_IN / 4)) return;
    int n = idx >> 5;          // /32
    int j = idx & 31;
    float4 v = ((const float4*)x)[(size_t)n * 32 + j];
    *((float4*)(g_TX + (size_t)n * TXW) + j) = v;
}

// mode 0: zero dst region ; mode 1: dst = -src region
__global__ void k_init_region(int dst_off, int src_off, int mode) {
    int idx = blockIdx.x * blockDim.x + threadIdx.x;   // over NN * F_IN
    if (idx >= NN * F_IN) return;
    int n = idx >> 7;
    int f = idx & 127;
    float v = 0.f;
    if (mode == 1) v = -g_TX[(size_t)n * TXW + src_off + f];
    g_TX[(size_t)n * TXW + dst_off + f] = v;
}

// out[dst] += coef * dinv[s] * dinv[d] * h[src]   (within g_TX regions, width 128)
__global__ void k_prop_cheb(const int* __restrict__ ei, int src_off, int dst_off, float coef) {
    int idx = blockIdx.x * blockDim.x + threadIdx.x;   // over EE * 32
    if (idx >= EE * 32) return;
    int e = idx >> 5;
    int j = idx & 31;
    int s = ei[e];
    int d = ei[EE + e];
    float w = coef * g_dinv_cheb[s] * g_dinv_cheb[d];
    float4 h = *(const float4*)(g_TX + (size_t)s * TXW + src_off + j * 4);
    float* o = g_TX + (size_t)d * TXW + dst_off + j * 4;
    atomicAdd(o + 0, w * h.x);
    atomicAdd(o + 1, w * h.y);
    atomicAdd(o + 2, w * h.z);
    atomicAdd(o + 3, w * h.w);
}

// ---------------- GCN aggregation --------------------------------------------
// dest[n,f] = dinv_gcn[n]^2 * h[n,f]   (self-loop folded into init)
__global__ void k_gcn_init(const float* __restrict__ h, float* __restrict__ dest, int C) {
    int idx = blockIdx.x * blockDim.x + threadIdx.x;
    if (idx >= NN * C) return;
    int n = idx / C;
    float di = g_dinv_gcn[n];
    dest[idx] = di * di * h[idx];
}

__global__ void k_gcn_edge(const int* __restrict__ ei,
                           const float* __restrict__ h, float* __restrict__ dest, int C) {
    int per = C >> 2;
    int idx = blockIdx.x * blockDim.x + threadIdx.x;   // EE * per
    if (idx >= EE * per) return;
    int e = idx / per;
    int j = idx - e * per;
    int s = ei[e];
    int d = ei[EE + e];
    float w = g_dinv_gcn[s] * g_dinv_gcn[d];
    float4 hv = *(const float4*)(h + (size_t)s * C + j * 4);
    float* o = dest + (size_t)d * C + j * 4;
    atomicAdd(o + 0, w * hv.x);
    atomicAdd(o + 1, w * hv.y);
    atomicAdd(o + 2, w * hv.z);
    atomicAdd(o + 3, w * hv.w);
}

__global__ void k_bias_relu(const float* __restrict__ in, const float* __restrict__ b,
                            float* __restrict__ out, int C) {
    int idx = blockIdx.x * blockDim.x + threadIdx.x;
    if (idx >= NN * C) return;
    int f = idx % C;
    out[idx] = fmaxf(in[idx] + b[f], 0.f);
}

// ---------------- GEMM: C[M,Nd] = A[M,Kd] @ B[Kd,Nd] (+bias)(+relu) ----------
// flags: bit0 = add bias, bit1 = relu
__global__ void k_gemm(const float* __restrict__ A, const float* __restrict__ B,
                       const float* __restrict__ bias, float* __restrict__ C,
                       int M, int Kd, int Nd, int flags) {
    const int BM = 64, BN = 64, BK = 16, TM = 4, TN = 4;
    __shared__ float As[BK][BM + 1];
    __shared__ float Bs[BK][BN + 1];
    int tid  = threadIdx.x;                // 256
    int brow = blockIdx.y * BM;
    int bcol = blockIdx.x * BN;
    int tr = (tid / 16) * TM;
    int tc = (tid % 16) * TN;
    float acc[TM][TN] = {};
    for (int k0 = 0; k0 < Kd; k0 += BK) {
        #pragma unroll
        for (int i = tid; i < BM * BK; i += 256) {
            int r = i / BK, c = i % BK;
            int gr = brow + r;
            As[c][r] = (gr < M) ? A[(size_t)gr * Kd + k0 + c] : 0.f;
        }
        #pragma unroll
        for (int i = tid; i < BK * BN; i += 256) {
            int r = i / BN, c = i % BN;
            Bs[r][c] = B[(size_t)(k0 + r) * Nd + bcol + c];
        }
        __syncthreads();
        #pragma unroll
        for (int kk = 0; kk < BK; kk++) {
            float a[TM], bb[TN];
            #pragma unroll
            for (int i = 0; i < TM; i++) a[i] = As[kk][tr + i];
            #pragma unroll
            for (int j = 0; j < TN; j++) bb[j] = Bs[kk][tc + j];
            #pragma unroll
            for (int i = 0; i < TM; i++)
                #pragma unroll
                for (int j = 0; j < TN; j++) acc[i][j] += a[i] * bb[j];
        }
        __syncthreads();
    }
    #pragma unroll
    for (int i = 0; i < TM; i++) {
        int gr = brow + tr + i;
        if (gr >= M) continue;
        #pragma unroll
        for (int j = 0; j < TN; j++) {
            int gc = bcol + tc + j;
            float v = acc[i][j];
            if (flags & 1) v += bias[gc];
            if (flags & 2) v = fmaxf(v, 0.f);
            C[(size_t)gr * Nd + gc] = v;
        }
    }
}

// ---------------- attention pooling ------------------------------------------
__global__ void k_logits(const float* __restrict__ h, const float* __restrict__ wg,
                         const float* __restrict__ bg) {
    int gtid = blockIdx.x * blockDim.x + threadIdx.x;
    int warp = gtid >> 5;
    int lane = gtid & 31;
    if (warp >= NN) return;
    float s = 0.f;
    for (int f = lane; f < C3D; f += 32) s += h[(size_t)warp * C3D + f] * wg[f];
    #pragma unroll
    for (int o = 16; o; o >>= 1) s += __shfl_xor_sync(0xffffffffu, s, o);
    if (lane == 0) g_e[warp] = s + bg[0];
}

__global__ void k_pool_init() {
    int i = blockIdx.x * blockDim.x + threadIdx.x;
    if (i < GG * C3D) g_pool[i] = 0.f;
    if (i < GG) { g_gmax[i] = -3.402823466e38f; g_gsum[i] = 0.f; }
}

__global__ void k_seg_max(const int* __restrict__ batch) {
    int n = blockIdx.x * blockDim.x + threadIdx.x;
    if (n >= NN) return;
    atomicMaxF(&g_gmax[batch[n]], g_e[n]);
}

__global__ void k_exp_sum(const int* __restrict__ batch) {
    int n = blockIdx.x * blockDim.x + threadIdx.x;
    if (n >= NN) return;
    int b = batch[n];
    float v = expf(g_e[n] - g_gmax[b]);
    g_e[n] = v;
    atomicAdd(&g_gsum[b], v);
}

__global__ void k_pool_scatter(const int* __restrict__ batch, const float* __restrict__ h) {
    int idx = blockIdx.x * blockDim.x + threadIdx.x;    // NN * (C3D/4)
    if (idx >= NN * (C3D / 4)) return;
    int n = idx >> 7;     // /128
    int j = idx & 127;
    int b = batch[n];
    float alpha = g_e[n] / g_gsum[b];
    float4 hv = *(const float4*)(h + (size_t)n * C3D + j * 4);
    float* o = g_pool + (size_t)b * C3D + j * 4;
    atomicAdd(o + 0, alpha * hv.x);
    atomicAdd(o + 1, alpha * hv.y);
    atomicAdd(o + 2, alpha * hv.z);
    atomicAdd(o + 3, alpha * hv.w);
}

__global__ void k_final(const float* __restrict__ Wfc, const float* __restrict__ bfc,
                        float* __restrict__ out) {
    int g = blockIdx.x;
    int lane = threadIdx.x;
    float lg[NCLS];
    #pragma unroll
    for (int c = 0; c < NCLS; c++) {
        float s = 0.f;
        for (int f = lane; f < C3D; f += 32)
            s += g_pool[(size_t)g * C3D + f] * Wfc[(size_t)f * NCLS + c];
        #pragma unroll
        for (int o = 16; o; o >>= 1) s += __shfl_xor_sync(0xffffffffu, s, o);
        lg[c] = s + bfc[c];
    }
    if (lane == 0) {
        float m = lg[0];
        #pragma unroll
        for (int c = 1; c < NCLS; c++) m = fmaxf(m, lg[c]);
        float ss = 0.f;
        #pragma unroll
        for (int c = 0; c < NCLS; c++) ss += expf(lg[c] - m);
        float lse = m + logf(ss);
        #pragma unroll
        for (int c = 0; c < NCLS; c++) out[(size_t)g * NCLS + c] = lg[c] - lse;
    }
}

// ---------------- launch ------------------------------------------------------
extern "C" void kernel_launch(void* const* d_in, const int* in_sizes, int n_in,
                              void* d_out, int out_size) {
    const float* x      = (const float*)d_in[0];
    const int*   ei     = (const int*)d_in[1];
    const int*   batch  = (const int*)d_in[2];
    const float* Wcheb  = (const float*)d_in[3];
    const float* bcheb  = (const float*)d_in[4];
    const float* Wg1    = (const float*)d_in[5];
    const float* bg1    = (const float*)d_in[6];
    const float* Wg2    = (const float*)d_in[7];
    const float* bg2    = (const float*)d_in[8];
    const float* wgate  = (const float*)d_in[9];
    const float* bgate  = (const float*)d_in[10];
    const float* Wfc    = (const float*)d_in[11];
    const float* bfc    = (const float*)d_in[12];
    float*       out    = (float*)d_out;

    float *pTX, *pA, *pB;
    cudaGetSymbolAddress((void**)&pTX, g_TX);
    cudaGetSymbolAddress((void**)&pA,  g_bufA);
    cudaGetSymbolAddress((void**)&pB,  g_bufB);

    const int T = 256;
    auto nb = [](long long n, int t) { return (int)((n + t - 1) / t); };

    // degrees / normalizations
    k_deg_init<<<nb(NN, T), T>>>();
    k_deg<<<nb(EE, T), T>>>(ei);
    k_dinv<<<nb(NN, T), T>>>();

    // Cheb: build TX = [Tx0 | Tx1 | Tx2 | Tx3 | Tx4]
    k_copy_x<<<nb((long long)NN * 32, T), T>>>(x);
    k_init_region<<<nb((long long)NN * F_IN, T), T>>>(1 * F_IN, 0, 0);
    k_prop_cheb<<<nb((long long)EE * 32, T), T>>>(ei, 0, 1 * F_IN, -1.0f);
    for (int k = 2; k < KCH; k++) {
        k_init_region<<<nb((long long)NN * F_IN, T), T>>>(k * F_IN, (k - 2) * F_IN, 1);
        k_prop_cheb<<<nb((long long)EE * 32, T), T>>>(ei, (k - 1) * F_IN, k * F_IN, -2.0f);
    }
    // h1 = relu(TX @ Wcheb[640,128] + b)
    k_gemm<<<dim3(C1D / 64, nb(NN, 64)), 256>>>(pTX, Wcheb, bcheb, pA, NN, TXW, C1D, 3);

    // GCN1: h = h1 @ Wg1 ; agg ; relu(+b)
    k_gemm<<<dim3(C2D / 64, nb(NN, 64)), 256>>>(pA, Wg1, nullptr, pB, NN, C1D, C2D, 0);
    k_gcn_init<<<nb((long long)NN * C2D, T), T>>>(pB, pTX, C2D);
    k_gcn_edge<<<nb((long long)EE * (C2D / 4), T), T>>>(ei, pB, pTX, C2D);
    k_bias_relu<<<nb((long long)NN * C2D, T), T>>>(pTX, bg1, pA, C2D);

    // GCN2
    k_gemm<<<dim3(C3D / 64, nb(NN, 64)), 256>>>(pA, Wg2, nullptr, pB, NN, C2D, C3D, 0);
    k_gcn_init<<<nb((long long)NN * C3D, T), T>>>(pB, pTX, C3D);
    k_gcn_edge<<<nb((long long)EE * (C3D / 4), T), T>>>(ei, pB, pTX, C3D);
    k_bias_relu<<<nb((long long)NN * C3D, T), T>>>(pTX, bg2, pA, C3D);

    // attention pooling
    k_logits<<<nb((long long)NN * 32, T), T>>>(pA, wgate, bgate);
    k_pool_init<<<nb(GG * C3D, T), T>>>();
    k_seg_max<<<nb(NN, T), T>>>(batch);
    k_exp_sum<<<nb(NN, T), T>>>(batch);
    k_pool_scatter<<<nb((long long)NN * (C3D / 4), T), T>>>(batch, pA);

    // FC + log_softmax
    k_final<<<GG, 32>>>(Wfc, bfc, out);
}

// round 3
// speedup vs baseline: 1.8523x; 1.8523x over previous
#include <cuda_runtime.h>

#define NN 10000
#define EE 160000
#define GG 64
#define F_IN 128
#define C1D 128
#define C2D 256
#define C3D 512
#define KCH 5
#define NCLS 10
#define TXW (KCH * F_IN)   // 640

// ---------------- scratch (device globals; no allocation allowed) ----------
__device__ int   g_cnt_in[NN];
__device__ int   g_cnt_out[NN];
__device__ int   g_cursor[NN];
__device__ int   g_row_ptr[NN + 1];
__device__ int   g_col[EE];
__device__ float g_wcheb[EE];
__device__ float g_wgcn[EE];
__device__ float g_dinv_cheb[NN];
__device__ float g_dinv_gcn[NN];
__device__ float g_TX[(size_t)NN * TXW];      // stacked Cheb Tx_k
__device__ float g_bufA[(size_t)NN * C3D];
__device__ float g_bufB[(size_t)NN * C3D];
__device__ float g_e[NN];                     // logits, then exp values
__device__ float g_gmax[GG];
__device__ float g_gsum[GG];
__device__ float g_pool[GG * C3D];

// ---------------- helpers ---------------------------------------------------
__device__ __forceinline__ void atomicMaxF(float* addr, float val) {
    int* ia = (int*)addr;
    int old = *ia;
    while (__int_as_float(old) < val) {
        int assumed = old;
        old = atomicCAS(ia, assumed, __float_as_int(val));
        if (old == assumed) break;
    }
}

// ---------------- CSR build --------------------------------------------------
__global__ void k_zero_csr() {
    int i = blockIdx.x * blockDim.x + threadIdx.x;
    if (i < NN) { g_cnt_in[i] = 0; g_cnt_out[i] = 0; g_cursor[i] = 0; }
}

__global__ void k_count(const int* __restrict__ ei) {
    int e = blockIdx.x * blockDim.x + threadIdx.x;
    if (e >= EE) return;
    atomicAdd(&g_cnt_out[ei[e]], 1);
    atomicAdd(&g_cnt_in[ei[EE + e]], 1);
}

__global__ void k_dinv() {
    int i = blockIdx.x * blockDim.x + threadIdx.x;
    if (i >= NN) return;
    int oc = g_cnt_out[i];
    g_dinv_cheb[i] = oc > 0 ? rsqrtf((float)oc) : 0.f;
    g_dinv_gcn[i]  = rsqrtf((float)(g_cnt_in[i] + 1));   // +1 self loop
}

// single-block exclusive scan of g_cnt_in -> g_row_ptr (NN+1 entries)
__global__ void k_scan() {
    __shared__ int part[1024];
    const int PER = (NN + 1023) / 1024;   // 10
    int tid = threadIdx.x;
    int base = tid * PER;
    int local[PER];
    int sum = 0;
    #pragma unroll
    for (int i = 0; i < PER; i++) {
        int idx = base + i;
        int v = (idx < NN) ? g_cnt_in[idx] : 0;
        local[i] = sum;
        sum += v;
    }
    part[tid] = sum;
    __syncthreads();
    for (int off = 1; off < 1024; off <<= 1) {
        int v = (tid >= off) ? part[tid - off] : 0;
        __syncthreads();
        part[tid] += v;
        __syncthreads();
    }
    int excl = (tid == 0) ? 0 : part[tid - 1];
    #pragma unroll
    for (int i = 0; i < PER; i++) {
        int idx = base + i;
        if (idx < NN) g_row_ptr[idx] = excl + local[i];
    }
    if (tid == 1023) g_row_ptr[NN] = part[1023];
}

__global__ void k_fill(const int* __restrict__ ei) {
    int e = blockIdx.x * blockDim.x + threadIdx.x;
    if (e >= EE) return;
    int s = ei[e];
    int d = ei[EE + e];
    int pos = g_row_ptr[d] + atomicAdd(&g_cursor[d], 1);
    g_col[pos]   = s;
    g_wcheb[pos] = -g_dinv_cheb[s] * g_dinv_cheb[d];
    g_wgcn[pos]  =  g_dinv_gcn[s]  * g_dinv_gcn[d];
}

// ---------------- Cheb pipeline ---------------------------------------------
__global__ void k_copy_x(const float* __restrict__ x) {
    int idx = blockIdx.x * blockDim.x + threadIdx.x;   // over NN * (F_IN/4)
    if (idx >= NN * (F_IN / 4)) return;
    int n = idx >> 5;
    int j = idx & 31;
    float4 v = ((const float4*)x)[(size_t)n * 32 + j];
    *((float4*)(g_TX + (size_t)n * TXW) + j) = v;
}

// mode 0: dst = prop(src)            (tx1)
// mode 1: dst = 2*prop(src) - tx0    (tx_k recurrence)
__global__ void k_gather_cheb(int src_off, int dst_off, int tx0_off, int mode) {
    // 8 nodes per 256-thread block; 1 warp per node; 1 float4 per lane (width 128)
    int n = blockIdx.x * 8 + (threadIdx.x >> 5);
    int j = threadIdx.x & 31;
    if (n >= NN) return;
    int beg = g_row_ptr[n], end = g_row_ptr[n + 1];
    float4 acc = {0.f, 0.f, 0.f, 0.f};
    #pragma unroll 2
    for (int r = beg; r < end; r++) {
        int s   = __ldg(&g_col[r]);
        float w = __ldg(&g_wcheb[r]);
        float4 h = *(const float4*)(g_TX + (size_t)s * TXW + src_off + j * 4);
        acc.x += w * h.x; acc.y += w * h.y; acc.z += w * h.z; acc.w += w * h.w;
    }
    float4 res;
    if (mode) {
        float4 t0 = *(const float4*)(g_TX + (size_t)n * TXW + tx0_off + j * 4);
        res.x = 2.f * acc.x - t0.x; res.y = 2.f * acc.y - t0.y;
        res.z = 2.f * acc.z - t0.z; res.w = 2.f * acc.w - t0.w;
    } else {
        res = acc;
    }
    *(float4*)(g_TX + (size_t)n * TXW + dst_off + j * 4) = res;
}

// ---------------- GCN gather (fused self-loop + bias + relu) ------------------
template <int C>
__global__ void k_gather_gcn(const float* __restrict__ h, const float* __restrict__ bias,
                             float* __restrict__ out) {
    constexpr int TPN = C / 4;            // threads per node
    constexpr int NPB = 256 / TPN;        // nodes per 256-thread block
    int local = threadIdx.x / TPN;
    int j     = threadIdx.x % TPN;
    int n = blockIdx.x * NPB + local;
    if (n >= NN) return;
    const float4* h4 = (const float4*)h;
    int beg = g_row_ptr[n], end = g_row_ptr[n + 1];
    float4 acc = {0.f, 0.f, 0.f, 0.f};
    #pragma unroll 2
    for (int r = beg; r < end; r++) {
        int s   = __ldg(&g_col[r]);
        float w = __ldg(&g_wgcn[r]);
        float4 hv = h4[(size_t)s * TPN + j];
        acc.x += w * hv.x; acc.y += w * hv.y; acc.z += w * hv.z; acc.w += w * hv.w;
    }
    float di = g_dinv_gcn[n];
    float sw = di * di;
    float4 self = h4[(size_t)n * TPN + j];
    float4 b4 = ((const float4*)bias)[j];
    float4 res;
    res.x = fmaxf(acc.x + sw * self.x + b4.x, 0.f);
    res.y = fmaxf(acc.y + sw * self.y + b4.y, 0.f);
    res.z = fmaxf(acc.z + sw * self.z + b4.z, 0.f);
    res.w = fmaxf(acc.w + sw * self.w + b4.w, 0.f);
    ((float4*)out)[(size_t)n * TPN + j] = res;
}

// ---------------- GEMM: C[M,Nd] = A[M,Kd] @ B[Kd,Nd] (+bias)(+relu) ----------
// flags: bit0 = add bias, bit1 = relu
__global__ void k_gemm(const float* __restrict__ A, const float* __restrict__ B,
                       const float* __restrict__ bias, float* __restrict__ C,
                       int M, int Kd, int Nd, int flags) {
    const int BM = 64, BN = 64, BK = 16, TM = 4, TN = 4;
    __shared__ float As[BK][BM + 1];
    __shared__ float Bs[BK][BN + 1];
    int tid  = threadIdx.x;                // 256
    int brow = blockIdx.y * BM;
    int bcol = blockIdx.x * BN;
    int tr = (tid / 16) * TM;
    int tc = (tid % 16) * TN;
    float acc[TM][TN] = {};
    for (int k0 = 0; k0 < Kd; k0 += BK) {
        #pragma unroll
        for (int i = tid; i < BM * BK; i += 256) {
            int r = i / BK, c = i % BK;
            int gr = brow + r;
            As[c][r] = (gr < M) ? A[(size_t)gr * Kd + k0 + c] : 0.f;
        }
        #pragma unroll
        for (int i = tid; i < BK * BN; i += 256) {
            int r = i / BN, c = i % BN;
            Bs[r][c] = B[(size_t)(k0 + r) * Nd + bcol + c];
        }
        __syncthreads();
        #pragma unroll
        for (int kk = 0; kk < BK; kk++) {
            float a[TM], bb[TN];
            #pragma unroll
            for (int i = 0; i < TM; i++) a[i] = As[kk][tr + i];
            #pragma unroll
            for (int j = 0; j < TN; j++) bb[j] = Bs[kk][tc + j];
            #pragma unroll
            for (int i = 0; i < TM; i++)
                #pragma unroll
                for (int j = 0; j < TN; j++) acc[i][j] += a[i] * bb[j];
        }
        __syncthreads();
    }
    #pragma unroll
    for (int i = 0; i < TM; i++) {
        int gr = brow + tr + i;
        if (gr >= M) continue;
        #pragma unroll
        for (int j = 0; j < TN; j++) {
            int gc = bcol + tc + j;
            float v = acc[i][j];
            if (flags & 1) v += bias[gc];
            if (flags & 2) v = fmaxf(v, 0.f);
            C[(size_t)gr * Nd + gc] = v;
        }
    }
}

// ---------------- attention pooling ------------------------------------------
__global__ void k_logits(const float* __restrict__ h, const float* __restrict__ wg,
                         const float* __restrict__ bg) {
    int gtid = blockIdx.x * blockDim.x + threadIdx.x;
    int warp = gtid >> 5;
    int lane = gtid & 31;
    if (warp >= NN) return;
    float s = 0.f;
    for (int f = lane; f < C3D; f += 32) s += h[(size_t)warp * C3D + f] * wg[f];
    #pragma unroll
    for (int o = 16; o; o >>= 1) s += __shfl_xor_sync(0xffffffffu, s, o);
    if (lane == 0) g_e[warp] = s + bg[0];
}

__global__ void k_pool_init() {
    int i = blockIdx.x * blockDim.x + threadIdx.x;
    if (i < GG * C3D) g_pool[i] = 0.f;
    if (i < GG) { g_gmax[i] = -3.402823466e38f; g_gsum[i] = 0.f; }
}

__global__ void k_seg_max(const int* __restrict__ batch) {
    int n = blockIdx.x * blockDim.x + threadIdx.x;
    if (n >= NN) return;
    atomicMaxF(&g_gmax[batch[n]], g_e[n]);
}

__global__ void k_exp_sum(const int* __restrict__ batch) {
    int n = blockIdx.x * blockDim.x + threadIdx.x;
    if (n >= NN) return;
    int b = batch[n];
    float v = expf(g_e[n] - g_gmax[b]);
    g_e[n] = v;
    atomicAdd(&g_gsum[b], v);
}

__global__ void k_pool_scatter(const int* __restrict__ batch, const float* __restrict__ h) {
    int idx = blockIdx.x * blockDim.x + threadIdx.x;    // NN * (C3D/4)
    if (idx >= NN * (C3D / 4)) return;
    int n = idx >> 7;
    int j = idx & 127;
    int b = batch[n];
    float alpha = g_e[n] / g_gsum[b];
    float4 hv = *(const float4*)(h + (size_t)n * C3D + j * 4);
    float* o = g_pool + (size_t)b * C3D + j * 4;
    atomicAdd(o + 0, alpha * hv.x);
    atomicAdd(o + 1, alpha * hv.y);
    atomicAdd(o + 2, alpha * hv.z);
    atomicAdd(o + 3, alpha * hv.w);
}

__global__ void k_final(const float* __restrict__ Wfc, const float* __restrict__ bfc,
                        float* __restrict__ out) {
    int g = blockIdx.x;
    int lane = threadIdx.x;
    float lg[NCLS];
    #pragma unroll
    for (int c = 0; c < NCLS; c++) {
        float s = 0.f;
        for (int f = lane; f < C3D; f += 32)
            s += g_pool[(size_t)g * C3D + f] * Wfc[(size_t)f * NCLS + c];
        #pragma unroll
        for (int o = 16; o; o >>= 1) s += __shfl_xor_sync(0xffffffffu, s, o);
        lg[c] = s + bfc[c];
    }
    if (lane == 0) {
        float m = lg[0];
        #pragma unroll
        for (int c = 1; c < NCLS; c++) m = fmaxf(m, lg[c]);
        float ss = 0.f;
        #pragma unroll
        for (int c = 0; c < NCLS; c++) ss += expf(lg[c] - m);
        float lse = m + logf(ss);
        #pragma unroll
        for (int c = 0; c < NCLS; c++) out[(size_t)g * NCLS + c] = lg[c] - lse;
    }
}

// ---------------- launch ------------------------------------------------------
extern "C" void kernel_launch(void* const* d_in, const int* in_sizes, int n_in,
                              void* d_out, int out_size) {
    const float* x      = (const float*)d_in[0];
    const int*   ei     = (const int*)d_in[1];
    const int*   batch  = (const int*)d_in[2];
    const float* Wcheb  = (const float*)d_in[3];
    const float* bcheb  = (const float*)d_in[4];
    const float* Wg1    = (const float*)d_in[5];
    const float* bg1    = (const float*)d_in[6];
    const float* Wg2    = (const float*)d_in[7];
    const float* bg2    = (const float*)d_in[8];
    const float* wgate  = (const float*)d_in[9];
    const float* bgate  = (const float*)d_in[10];
    const float* Wfc    = (const float*)d_in[11];
    const float* bfc    = (const float*)d_in[12];
    float*       out    = (float*)d_out;

    float *pTX, *pA, *pB;
    cudaGetSymbolAddress((void**)&pTX, g_TX);
    cudaGetSymbolAddress((void**)&pA,  g_bufA);
    cudaGetSymbolAddress((void**)&pB,  g_bufB);

    const int T = 256;
    auto nb = [](long long n, int t) { return (int)((n + t - 1) / t); };

    // ---- CSR build (dst-sorted; shared by all prop layers) ----
    k_zero_csr<<<nb(NN, T), T>>>();
    k_count<<<nb(EE, T), T>>>(ei);
    k_dinv<<<nb(NN, T), T>>>();
    k_scan<<<1, 1024>>>();
    k_fill<<<nb(EE, T), T>>>(ei);

    // ---- Cheb: TX = [Tx0 | Tx1 | Tx2 | Tx3 | Tx4] ----
    k_copy_x<<<nb((long long)NN * 32, T), T>>>(x);
    k_gather_cheb<<<nb(NN, 8), 256>>>(0, 1 * F_IN, 0, 0);
    k_gather_cheb<<<nb(NN, 8), 256>>>(1 * F_IN, 2 * F_IN, 0 * F_IN, 1);
    k_gather_cheb<<<nb(NN, 8), 256>>>(2 * F_IN, 3 * F_IN, 1 * F_IN, 1);
    k_gather_cheb<<<nb(NN, 8), 256>>>(3 * F_IN, 4 * F_IN, 2 * F_IN, 1);
    // h1 = relu(TX @ Wcheb[640,128] + b)
    k_gemm<<<dim3(C1D / 64, nb(NN, 64)), 256>>>(pTX, Wcheb, bcheb, pA, NN, TXW, C1D, 3);

    // ---- GCN1: transform, gather(+self+bias+relu) ----
    k_gemm<<<dim3(C2D / 64, nb(NN, 64)), 256>>>(pA, Wg1, nullptr, pB, NN, C1D, C2D, 0);
    k_gather_gcn<C2D><<<nb(NN, 4), 256>>>(pB, bg1, pA);

    // ---- GCN2 ----
    k_gemm<<<dim3(C3D / 64, nb(NN, 64)), 256>>>(pA, Wg2, nullptr, pB, NN, C2D, C3D, 0);
    k_gather_gcn<C3D><<<nb(NN, 2), 256>>>(pB, bg2, pA);

    // ---- attention pooling ----
    k_logits<<<nb((long long)NN * 32, T), T>>>(pA, wgate, bgate);
    k_pool_init<<<nb(GG * C3D, T), T>>>();
    k_seg_max<<<nb(NN, T), T>>>(batch);
    k_exp_sum<<<nb(NN, T), T>>>(batch);
    k_pool_scatter<<<nb((long long)NN * (C3D / 4), T), T>>>(batch, pA);

    // ---- FC + log_softmax ----
    k_final<<<GG, 32>>>(Wfc, bfc, out);
}

// round 4
// speedup vs baseline: 3.1802x; 1.7168x over previous
#include <cuda_runtime.h>
#include <cuda_bf16.h>

#define NN 10000
#define EE 160000
#define GG 64
#define F_IN 128
#define C1D 128
#define C2D 256
#define C3D 512
#define KCH 5
#define NCLS 10
#define TXW (KCH * F_IN)   // 640

// ---------------- scratch (device globals; no allocation allowed) ----------
__device__ int   g_cnt_in[NN];
__device__ int   g_cnt_out[NN];
__device__ int   g_cursor[NN];
__device__ int   g_row_ptr[NN + 1];
__device__ int   g_col[EE];
__device__ float g_wcheb[EE];
__device__ float g_wgcn[EE];
__device__ float g_dinv_cheb[NN];
__device__ float g_dinv_gcn[NN];
__device__ float g_TX[(size_t)NN * TXW];      // stacked Cheb Tx_k
__device__ float g_bufA[(size_t)NN * C3D];
__device__ float g_bufB[(size_t)NN * C3D];
__device__ float g_e[NN];
__device__ float g_gmax[GG];
__device__ float g_gsum[GG];
__device__ float g_pool[GG * C3D];

// ---------------- helpers ---------------------------------------------------
__device__ __forceinline__ void atomicMaxF(float* addr, float val) {
    int* ia = (int*)addr;
    int old = *ia;
    while (__int_as_float(old) < val) {
        int assumed = old;
        old = atomicCAS(ia, assumed, __float_as_int(val));
        if (old == assumed) break;
    }
}

// ---------------- CSR build --------------------------------------------------
__global__ void k_zero_csr() {
    int i = blockIdx.x * blockDim.x + threadIdx.x;
    if (i < NN) { g_cnt_in[i] = 0; g_cnt_out[i] = 0; g_cursor[i] = 0; }
}

__global__ void k_count(const int* __restrict__ ei) {
    int e = blockIdx.x * blockDim.x + threadIdx.x;
    if (e >= EE) return;
    atomicAdd(&g_cnt_out[ei[e]], 1);
    atomicAdd(&g_cnt_in[ei[EE + e]], 1);
}

__global__ void k_dinv() {
    int i = blockIdx.x * blockDim.x + threadIdx.x;
    if (i >= NN) return;
    int oc = g_cnt_out[i];
    g_dinv_cheb[i] = oc > 0 ? rsqrtf((float)oc) : 0.f;
    g_dinv_gcn[i]  = rsqrtf((float)(g_cnt_in[i] + 1));   // +1 self loop
}

// single-block exclusive scan of g_cnt_in -> g_row_ptr (NN+1 entries)
__global__ void k_scan() {
    __shared__ int part[1024];
    const int PER = (NN + 1023) / 1024;   // 10
    int tid = threadIdx.x;
    int base = tid * PER;
    int local[PER];
    int sum = 0;
    #pragma unroll
    for (int i = 0; i < PER; i++) {
        int idx = base + i;
        int v = (idx < NN) ? g_cnt_in[idx] : 0;
        local[i] = sum;
        sum += v;
    }
    part[tid] = sum;
    __syncthreads();
    for (int off = 1; off < 1024; off <<= 1) {
        int v = (tid >= off) ? part[tid - off] : 0;
        __syncthreads();
        part[tid] += v;
        __syncthreads();
    }
    int excl = (tid == 0) ? 0 : part[tid - 1];
    #pragma unroll
    for (int i = 0; i < PER; i++) {
        int idx = base + i;
        if (idx < NN) g_row_ptr[idx] = excl + local[i];
    }
    if (tid == 1023) g_row_ptr[NN] = part[1023];
}

__global__ void k_fill(const int* __restrict__ ei) {
    int e = blockIdx.x * blockDim.x + threadIdx.x;
    if (e >= EE) return;
    int s = ei[e];
    int d = ei[EE + e];
    int pos = g_row_ptr[d] + atomicAdd(&g_cursor[d], 1);
    g_col[pos]   = s;
    g_wcheb[pos] = -g_dinv_cheb[s] * g_dinv_cheb[d];
    g_wgcn[pos]  =  g_dinv_gcn[s]  * g_dinv_gcn[d];
}

// ---------------- Cheb pipeline ---------------------------------------------
__global__ void k_copy_x(const float* __restrict__ x) {
    int idx = blockIdx.x * blockDim.x + threadIdx.x;
    if (idx >= NN * (F_IN / 4)) return;
    int n = idx >> 5;
    int j = idx & 31;
    float4 v = ((const float4*)x)[(size_t)n * 32 + j];
    *((float4*)(g_TX + (size_t)n * TXW) + j) = v;
}

// mode 0: dst = prop(src) ; mode 1: dst = 2*prop(src) - tx0
__global__ void k_gather_cheb(int src_off, int dst_off, int tx0_off, int mode) {
    int n = blockIdx.x * 8 + (threadIdx.x >> 5);
    int j = threadIdx.x & 31;
    if (n >= NN) return;
    int beg = g_row_ptr[n], end = g_row_ptr[n + 1];
    float4 acc = {0.f, 0.f, 0.f, 0.f};
    #pragma unroll 2
    for (int r = beg; r < end; r++) {
        int s   = __ldg(&g_col[r]);
        float w = __ldg(&g_wcheb[r]);
        float4 h = *(const float4*)(g_TX + (size_t)s * TXW + src_off + j * 4);
        acc.x += w * h.x; acc.y += w * h.y; acc.z += w * h.z; acc.w += w * h.w;
    }
    float4 res;
    if (mode) {
        float4 t0 = *(const float4*)(g_TX + (size_t)n * TXW + tx0_off + j * 4);
        res.x = 2.f * acc.x - t0.x; res.y = 2.f * acc.y - t0.y;
        res.z = 2.f * acc.z - t0.z; res.w = 2.f * acc.w - t0.w;
    } else {
        res = acc;
    }
    *(float4*)(g_TX + (size_t)n * TXW + dst_off + j * 4) = res;
}

// ---------------- GCN gather (fused self-loop + bias + relu) ------------------
template <int C>
__global__ void k_gather_gcn(const float* __restrict__ h, const float* __restrict__ bias,
                             float* __restrict__ out) {
    constexpr int TPN = C / 4;
    constexpr int NPB = 256 / TPN;
    int local = threadIdx.x / TPN;
    int j     = threadIdx.x % TPN;
    int n = blockIdx.x * NPB + local;
    if (n >= NN) return;
    const float4* h4 = (const float4*)h;
    int beg = g_row_ptr[n], end = g_row_ptr[n + 1];
    float4 acc = {0.f, 0.f, 0.f, 0.f};
    #pragma unroll 2
    for (int r = beg; r < end; r++) {
        int s   = __ldg(&g_col[r]);
        float w = __ldg(&g_wgcn[r]);
        float4 hv = h4[(size_t)s * TPN + j];
        acc.x += w * hv.x; acc.y += w * hv.y; acc.z += w * hv.z; acc.w += w * hv.w;
    }
    float di = g_dinv_gcn[n];
    float sw = di * di;
    float4 self = h4[(size_t)n * TPN + j];
    float4 b4 = ((const float4*)bias)[j];
    float4 res;
    res.x = fmaxf(acc.x + sw * self.x + b4.x, 0.f);
    res.y = fmaxf(acc.y + sw * self.y + b4.y, 0.f);
    res.z = fmaxf(acc.z + sw * self.z + b4.z, 0.f);
    res.w = fmaxf(acc.w + sw * self.w + b4.w, 0.f);
    ((float4*)out)[(size_t)n * TPN + j] = res;
}

// ---------------- bf16x3 tensor-core GEMM ------------------------------------
// C[M,Nd] = A[M,Kd] @ B[Kd,Nd] (+bias)(+relu), fp32 in/out.
// A,B split into bf16 hi+lo; D += Ah*Bh + Ah*Bl + Al*Bh (error ~2^-18).
// BM=128, BN=64, BK=32; 256 threads = 8 warps (4M x 2N), warp tile 32x32.
#define GBM 128
#define GBN 64
#define GBK 32

__device__ __forceinline__ void mma_bf16(float c[4], unsigned a0, unsigned a1,
                                         unsigned a2, unsigned a3,
                                         unsigned b0, unsigned b1) {
    asm volatile(
        "mma.sync.aligned.m16n8k16.row.col.f32.bf16.bf16.f32 "
        "{%0,%1,%2,%3}, {%4,%5,%6,%7}, {%8,%9}, {%0,%1,%2,%3};"
        : "+f"(c[0]), "+f"(c[1]), "+f"(c[2]), "+f"(c[3])
        : "r"(a0), "r"(a1), "r"(a2), "r"(a3), "r"(b0), "r"(b1));
}

__device__ __forceinline__ void split_bf16(float v, __nv_bfloat16& hi, __nv_bfloat16& lo) {
    hi = __float2bfloat16(v);
    lo = __float2bfloat16(v - __bfloat162float(hi));
}

__global__ __launch_bounds__(256, 2)
void k_gemm_tc(const float* __restrict__ A, const float* __restrict__ B,
               const float* __restrict__ bias, float* __restrict__ C,
               int M, int Kd, int Nd, int flags) {
    __shared__ __nv_bfloat16 Ah[GBM][GBK + 2];   // row-major, k contiguous
    __shared__ __nv_bfloat16 Al[GBM][GBK + 2];
    __shared__ __nv_bfloat16 Bh[GBN][GBK + 2];   // transposed: n rows, k contiguous
    __shared__ __nv_bfloat16 Bl[GBN][GBK + 2];

    int tid = threadIdx.x;
    int wid = tid >> 5, lane = tid & 31;
    int wm = wid >> 1, wn = wid & 1;             // 4 x 2 warp grid
    int g = lane >> 2, tg = lane & 3;
    int brow = blockIdx.y * GBM;
    int bcol = blockIdx.x * GBN;

    float acc[2][4][4];
    #pragma unroll
    for (int a = 0; a < 2; a++)
        #pragma unroll
        for (int b = 0; b < 4; b++)
            #pragma unroll
            for (int c = 0; c < 4; c++) acc[a][b][c] = 0.f;

    // staging indices
    int arow = tid >> 3;               // 0..31 (+32 x4)
    int acol = (tid & 7) * 4;
    int bkr  = tid >> 4;               // 0..15 (+16 x2)
    int bnc  = (tid & 15) * 4;

    for (int k0 = 0; k0 < Kd; k0 += GBK) {
        // ---- stage A tile [GBM][GBK] ----
        #pragma unroll
        for (int i = 0; i < 4; i++) {
            int r = arow + i * 32;
            int gr = brow + r;
            float4 v = (gr < M) ? *(const float4*)(A + (size_t)gr * Kd + k0 + acol)
                                : make_float4(0.f, 0.f, 0.f, 0.f);
            __nv_bfloat16 h0, l0, h1, l1, h2, l2, h3, l3;
            split_bf16(v.x, h0, l0); split_bf16(v.y, h1, l1);
            split_bf16(v.z, h2, l2); split_bf16(v.w, h3, l3);
            *(__nv_bfloat162*)&Ah[r][acol]     = __nv_bfloat162(h0, h1);
            *(__nv_bfloat162*)&Ah[r][acol + 2] = __nv_bfloat162(h2, h3);
            *(__nv_bfloat162*)&Al[r][acol]     = __nv_bfloat162(l0, l1);
            *(__nv_bfloat162*)&Al[r][acol + 2] = __nv_bfloat162(l2, l3);
        }
        // ---- stage B tile [GBK][GBN] transposed into [GBN][GBK] ----
        #pragma unroll
        for (int i = 0; i < 2; i++) {
            int kk = bkr + i * 16;
            float4 v = *(const float4*)(B + (size_t)(k0 + kk) * Nd + bcol + bnc);
            __nv_bfloat16 hi, lo;
            split_bf16(v.x, hi, lo); Bh[bnc + 0][kk] = hi; Bl[bnc + 0][kk] = lo;
            split_bf16(v.y, hi, lo); Bh[bnc + 1][kk] = hi; Bl[bnc + 1][kk] = lo;
            split_bf16(v.z, hi, lo); Bh[bnc + 2][kk] = hi; Bl[bnc + 2][kk] = lo;
            split_bf16(v.w, hi, lo); Bh[bnc + 3][kk] = hi; Bl[bnc + 3][kk] = lo;
        }
        __syncthreads();

        #pragma unroll
        for (int ks = 0; ks < 2; ks++) {
            int kb = ks * 16;
            unsigned ah[2][4], al[2][4];
            #pragma unroll
            for (int mf = 0; mf < 2; mf++) {
                int row = wm * 32 + mf * 16;
                ah[mf][0] = *(const unsigned*)&Ah[row + g][kb + 2 * tg];
                ah[mf][1] = *(const unsigned*)&Ah[row + g + 8][kb + 2 * tg];
                ah[mf][2] = *(const unsigned*)&Ah[row + g][kb + 2 * tg + 8];
                ah[mf][3] = *(const unsigned*)&Ah[row + g + 8][kb + 2 * tg + 8];
                al[mf][0] = *(const unsigned*)&Al[row + g][kb + 2 * tg];
                al[mf][1] = *(const unsigned*)&Al[row + g + 8][kb + 2 * tg];
                al[mf][2] = *(const unsigned*)&Al[row + g][kb + 2 * tg + 8];
                al[mf][3] = *(const unsigned*)&Al[row + g + 8][kb + 2 * tg + 8];
            }
            #pragma unroll
            for (int nf = 0; nf < 4; nf++) {
                int nn = wn * 32 + nf * 8 + g;
                unsigned bh0 = *(const unsigned*)&Bh[nn][kb + 2 * tg];
                unsigned bh1 = *(const unsigned*)&Bh[nn][kb + 2 * tg + 8];
                unsigned bl0 = *(const unsigned*)&Bl[nn][kb + 2 * tg];
                unsigned bl1 = *(const unsigned*)&Bl[nn][kb + 2 * tg + 8];
                #pragma unroll
                for (int mf = 0; mf < 2; mf++) {
                    mma_bf16(acc[mf][nf], ah[mf][0], ah[mf][1], ah[mf][2], ah[mf][3], bh0, bh1);
                    mma_bf16(acc[mf][nf], ah[mf][0], ah[mf][1], ah[mf][2], ah[mf][3], bl0, bl1);
                    mma_bf16(acc[mf][nf], al[mf][0], al[mf][1], al[mf][2], al[mf][3], bh0, bh1);
                }
            }
        }
        __syncthreads();
    }

    // ---- epilogue ----
    #pragma unroll
    for (int mf = 0; mf < 2; mf++) {
        int gr0 = brow + wm * 32 + mf * 16 + g;
        #pragma unroll
        for (int nf = 0; nf < 4; nf++) {
            int gc = bcol + wn * 32 + nf * 8 + 2 * tg;
            float b0 = 0.f, b1 = 0.f;
            if (flags & 1) { b0 = bias[gc]; b1 = bias[gc + 1]; }
            float v0 = acc[mf][nf][0] + b0;
            float v1 = acc[mf][nf][1] + b1;
            float v2 = acc[mf][nf][2] + b0;
            float v3 = acc[mf][nf][3] + b1;
            if (flags & 2) {
                v0 = fmaxf(v0, 0.f); v1 = fmaxf(v1, 0.f);
                v2 = fmaxf(v2, 0.f); v3 = fmaxf(v3, 0.f);
            }
            if (gr0 < M)     *(float2*)(C + (size_t)gr0 * Nd + gc)       = make_float2(v0, v1);
            if (gr0 + 8 < M) *(float2*)(C + (size_t)(gr0 + 8) * Nd + gc) = make_float2(v2, v3);
        }
    }
}

// ---------------- attention pooling ------------------------------------------
__global__ void k_logits(const float* __restrict__ h, const float* __restrict__ wg,
                         const float* __restrict__ bg) {
    int gtid = blockIdx.x * blockDim.x + threadIdx.x;
    int warp = gtid >> 5;
    int lane = gtid & 31;
    if (warp >= NN) return;
    float s = 0.f;
    for (int f = lane; f < C3D; f += 32) s += h[(size_t)warp * C3D + f] * wg[f];
    #pragma unroll
    for (int o = 16; o; o >>= 1) s += __shfl_xor_sync(0xffffffffu, s, o);
    if (lane == 0) g_e[warp] = s + bg[0];
}

__global__ void k_pool_init() {
    int i = blockIdx.x * blockDim.x + threadIdx.x;
    if (i < GG * C3D) g_pool[i] = 0.f;
    if (i < GG) { g_gmax[i] = -3.402823466e38f; g_gsum[i] = 0.f; }
}

__global__ void k_seg_max(const int* __restrict__ batch) {
    int n = blockIdx.x * blockDim.x + threadIdx.x;
    if (n >= NN) return;
    atomicMaxF(&g_gmax[batch[n]], g_e[n]);
}

__global__ void k_exp_sum(const int* __restrict__ batch) {
    int n = blockIdx.x * blockDim.x + threadIdx.x;
    if (n >= NN) return;
    int b = batch[n];
    float v = expf(g_e[n] - g_gmax[b]);
    g_e[n] = v;
    atomicAdd(&g_gsum[b], v);
}

__global__ void k_pool_scatter(const int* __restrict__ batch, const float* __restrict__ h) {
    int idx = blockIdx.x * blockDim.x + threadIdx.x;
    if (idx >= NN * (C3D / 4)) return;
    int n = idx >> 7;
    int j = idx & 127;
    int b = batch[n];
    float alpha = g_e[n] / g_gsum[b];
    float4 hv = *(const float4*)(h + (size_t)n * C3D + j * 4);
    float* o = g_pool + (size_t)b * C3D + j * 4;
    atomicAdd(o + 0, alpha * hv.x);
    atomicAdd(o + 1, alpha * hv.y);
    atomicAdd(o + 2, alpha * hv.z);
    atomicAdd(o + 3, alpha * hv.w);
}

__global__ void k_final(const float* __restrict__ Wfc, const float* __restrict__ bfc,
                        float* __restrict__ out) {
    int g = blockIdx.x;
    int lane = threadIdx.x;
    float lg[NCLS];
    #pragma unroll
    for (int c = 0; c < NCLS; c++) {
        float s = 0.f;
        for (int f = lane; f < C3D; f += 32)
            s += g_pool[(size_t)g * C3D + f] * Wfc[(size_t)f * NCLS + c];
        #pragma unroll
        for (int o = 16; o; o >>= 1) s += __shfl_xor_sync(0xffffffffu, s, o);
        lg[c] = s + bfc[c];
    }
    if (lane == 0) {
        float m = lg[0];
        #pragma unroll
        for (int c = 1; c < NCLS; c++) m = fmaxf(m, lg[c]);
        float ss = 0.f;
        #pragma unroll
        for (int c = 0; c < NCLS; c++) ss += expf(lg[c] - m);
        float lse = m + logf(ss);
        #pragma unroll
        for (int c = 0; c < NCLS; c++) out[(size_t)g * NCLS + c] = lg[c] - lse;
    }
}

// ---------------- launch ------------------------------------------------------
extern "C" void kernel_launch(void* const* d_in, const int* in_sizes, int n_in,
                              void* d_out, int out_size) {
    const float* x      = (const float*)d_in[0];
    const int*   ei     = (const int*)d_in[1];
    const int*   batch  = (const int*)d_in[2];
    const float* Wcheb  = (const float*)d_in[3];
    const float* bcheb  = (const float*)d_in[4];
    const float* Wg1    = (const float*)d_in[5];
    const float* bg1    = (const float*)d_in[6];
    const float* Wg2    = (const float*)d_in[7];
    const float* bg2    = (const float*)d_in[8];
    const float* wgate  = (const float*)d_in[9];
    const float* bgate  = (const float*)d_in[10];
    const float* Wfc    = (const float*)d_in[11];
    const float* bfc    = (const float*)d_in[12];
    float*       out    = (float*)d_out;

    float *pTX, *pA, *pB;
    cudaGetSymbolAddress((void**)&pTX, g_TX);
    cudaGetSymbolAddress((void**)&pA,  g_bufA);
    cudaGetSymbolAddress((void**)&pB,  g_bufB);

    const int T = 256;
    auto nb = [](long long n, int t) { return (int)((n + t - 1) / t); };

    // ---- CSR build ----
    k_zero_csr<<<nb(NN, T), T>>>();
    k_count<<<nb(EE, T), T>>>(ei);
    k_dinv<<<nb(NN, T), T>>>();
    k_scan<<<1, 1024>>>();
    k_fill<<<nb(EE, T), T>>>(ei);

    // ---- Cheb ----
    k_copy_x<<<nb((long long)NN * 32, T), T>>>(x);
    k_gather_cheb<<<nb(NN, 8), 256>>>(0, 1 * F_IN, 0, 0);
    k_gather_cheb<<<nb(NN, 8), 256>>>(1 * F_IN, 2 * F_IN, 0 * F_IN, 1);
    k_gather_cheb<<<nb(NN, 8), 256>>>(2 * F_IN, 3 * F_IN, 1 * F_IN, 1);
    k_gather_cheb<<<nb(NN, 8), 256>>>(3 * F_IN, 4 * F_IN, 2 * F_IN, 1);
    k_gemm_tc<<<dim3(C1D / GBN, nb(NN, GBM)), 256>>>(pTX, Wcheb, bcheb, pA, NN, TXW, C1D, 3);

    // ---- GCN1 ----
    k_gemm_tc<<<dim3(C2D / GBN, nb(NN, GBM)), 256>>>(pA, Wg1, nullptr, pB, NN, C1D, C2D, 0);
    k_gather_gcn<C2D><<<nb(NN, 4), 256>>>(pB, bg1, pA);

    // ---- GCN2 ----
    k_gemm_tc<<<dim3(C3D / GBN, nb(NN, GBM)), 256>>>(pA, Wg2, nullptr, pB, NN, C2D, C3D, 0);
    k_gather_gcn<C3D><<<nb(NN, 2), 256>>>(pB, bg2, pA);

    // ---- attention pooling ----
    k_logits<<<nb((long long)NN * 32, T), T>>>(pA, wgate, bgate);
    k_pool_init<<<nb(GG * C3D, T), T>>>();
    k_seg_max<<<nb(NN, T), T>>>(batch);
    k_exp_sum<<<nb(NN, T), T>>>(batch);
    k_pool_scatter<<<nb((long long)NN * (C3D / 4), T), T>>>(batch, pA);

    // ---- FC + log_softmax ----
    k_final<<<GG, 32>>>(Wfc, bfc, out);
}